// round 11
// baseline (speedup 1.0000x reference)
#include <cuda_runtime.h>
#include <cuda_fp16.h>
#include <math.h>
#include <stdint.h>

#define BB 32
#define TU 128
#define TM 128
#define TZ 32
#define TT 288          // TU+TM+TZ
#define HH 512
#define EE 128
#define SS 640          // E+H
#define VV 10000
#define NROW_P 9216     // BB*(TU+TM+TZ)

// ---------------- scratch (device globals; no allocation allowed) ----------
__device__ float g_hidp[BB*HH];
__device__ float g_s[BB*TT];
__device__ float g_x[BB*SS];
__device__ float g_gi[BB*3*HH];
__device__ float g_gh[BB*3*HH];
__device__ float g_h[BB*HH];
__device__ float g_st[BB*SS];
__device__ float g_sc[NROW_P];
__device__ float g_sg[BB*VV];
__device__ float2 g_red[BB];

// fp16 converted operands
__device__ __half h_uh[BB*TU*HH];
__device__ __half h_mh[BB*TM*HH];
__device__ __half h_pzh[BB*TZ*HH];
__device__ __half h_Wattn[HH*2*HH];
__device__ __half h_Wih[3*HH*SS];
__device__ __half h_Whh[3*HH*HH];
__device__ __half h_Wgen[VV*SS];
__device__ __half h_Wcpu[SS*HH];
__device__ __half h_Wcpm[SS*HH];
__device__ __half h_Wcppz[SS*HH];

// ---------------- helpers ---------------------------------------------------
__device__ __forceinline__ uint32_t s2u(const void* p) {
    unsigned a;
    asm("{ .reg .u64 t; cvta.to.shared.u64 t, %1; cvt.u32.u64 %0, t; }" : "=r"(a) : "l"(p));
    return a;
}

#define LDSM4(r0, r1, r2, r3, a) \
    asm volatile("ldmatrix.sync.aligned.m8n8.x4.shared.b16 {%0,%1,%2,%3}, [%4];" \
                 : "=r"(r0), "=r"(r1), "=r"(r2), "=r"(r3) : "r"(a))

__device__ __forceinline__ void mma16(float* c, const unsigned* a, const unsigned* b) {
    asm volatile(
        "mma.sync.aligned.m16n8k16.row.col.f32.f16.f16.f32 "
        "{%0,%1,%2,%3}, {%4,%5,%6,%7}, {%8,%9}, {%0,%1,%2,%3};\n"
        : "+f"(c[0]), "+f"(c[1]), "+f"(c[2]), "+f"(c[3])
        : "r"(a[0]), "r"(a[1]), "r"(a[2]), "r"(a[3]), "r"(b[0]), "r"(b[1]));
}

#define CPA(sm, gm, ok) \
    asm volatile("cp.async.ca.shared.global [%0], [%1], 16, %2;\n" \
                 :: "r"(sm), "l"(gm), "r"((ok) ? 16 : 0) : "memory")
#define CPCOMMIT asm volatile("cp.async.commit_group;\n" ::: "memory")
#define CPWAIT0  asm volatile("cp.async.wait_group 0;\n" ::: "memory")

// ---------------- fp32 -> fp16 conversion (2 batched kernels) --------------
__global__ void cvt_act(const float4* __restrict__ u, const float4* __restrict__ m,
                        const float4* __restrict__ pz, const float4* __restrict__ wa)
{
    size_t i = (size_t)blockIdx.x*256 + threadIdx.x;
    const size_t n0 = 524288, n1 = n0 + 524288, n2 = n1 + 131072, n3 = n2 + 131072;
    const float4* src; __half2* dst; size_t off;
    if (i < n0)      { src = u;  dst = (__half2*)h_uh;    off = i; }
    else if (i < n1) { src = m;  dst = (__half2*)h_mh;    off = i - n0; }
    else if (i < n2) { src = pz; dst = (__half2*)h_pzh;   off = i - n1; }
    else if (i < n3) { src = wa; dst = (__half2*)h_Wattn; off = i - n2; }
    else return;
    float4 v = src[off];
    __half2 a = __floats2half2_rn(v.x, v.y), b = __floats2half2_rn(v.z, v.w);
    uint2 o; o.x = *(unsigned*)&a; o.y = *(unsigned*)&b;
    *(uint2*)&dst[2*off] = o;
}

__global__ void cvt_rest(const float4* __restrict__ wih, const float4* __restrict__ whh,
                         const float4* __restrict__ wgen, const float4* __restrict__ wcu,
                         const float4* __restrict__ wcm, const float4* __restrict__ wcz)
{
    size_t i = (size_t)blockIdx.x*256 + threadIdx.x;
    const size_t n0 = 245760, n1 = n0+196608, n2 = n1+1600000,
                 n3 = n2+81920, n4 = n3+81920, n5 = n4+81920;
    const float4* src; __half2* dst; size_t off;
    if (i < n0)      { src = wih;  dst = (__half2*)h_Wih;   off = i; }
    else if (i < n1) { src = whh;  dst = (__half2*)h_Whh;   off = i - n0; }
    else if (i < n2) { src = wgen; dst = (__half2*)h_Wgen;  off = i - n1; }
    else if (i < n3) { src = wcu;  dst = (__half2*)h_Wcpu;  off = i - n2; }
    else if (i < n4) { src = wcm;  dst = (__half2*)h_Wcpm;  off = i - n3; }
    else if (i < n5) { src = wcz;  dst = (__half2*)h_Wcppz; off = i - n4; }
    else return;
    float4 v = src[off];
    __half2 a = __floats2half2_rn(v.x, v.y), b = __floats2half2_rn(v.z, v.w);
    uint2 o; o.x = *(unsigned*)&a; o.y = *(unsigned*)&b;
    *(uint2*)&dst[2*off] = o;
}

// hidp = h0 @ W1^T + b_attn  (SIMT, fp32, one block per output column g)
__global__ void hidp_k(const float* __restrict__ h0, const float* __restrict__ W,
                       const float* __restrict__ bias, float* __restrict__ out)
{
    int g = blockIdx.x;                 // 0..511
    __shared__ float w[HH];
    for (int i = threadIdx.x; i < HH; i += 256) w[i] = W[(size_t)g*2*HH + i];
    __syncthreads();
    int b = threadIdx.x >> 3, idx = threadIdx.x & 7;
    const float* h = h0 + b*HH;
    float p = 0.f;
    #pragma unroll 8
    for (int i = idx*64; i < idx*64 + 64; i++) p += h[i] * w[i];
    p += __shfl_down_sync(0xffffffff, p, 4);
    p += __shfl_down_sync(0xffffffff, p, 2);
    p += __shfl_down_sync(0xffffffff, p, 1);
    if (idx == 0) out[b*HH + g] = p + bias[g];
}

// ============== 128x128 fp16 GEMM body (cp.async + ldmatrix, 2-stage) =======
// ACT 2: atomicAdd(C[b*sStride + sOff + t], sum_n tanh(acc + aux[b*N+n])*vvec[n])
// ACT 3: atomicAdd(C[r], sum_n tanh(acc + bias[n]) * aux[b*N+n]), b = r/rows_per_b
template<int ACT>
__device__ __forceinline__ void
gemmh_body(const __half* __restrict__ A, int lda,
           const __half* __restrict__ B, int ldb,
           const float* __restrict__ bias,
           const float* __restrict__ aux,
           const float* __restrict__ vvec,
           float* __restrict__ C,
           int M, int N, int K, int rows_per_b,
           int m0, int n0, int sOff, int sStride)
{
    __shared__ __half2 As[2][128][20];   // 80B rows, stage stride 10240 B
    __shared__ __half2 Bs[2][128][20];

    const int t    = threadIdx.x;
    const int warp = t >> 5;
    const int lane = t & 31;
    const int wm   = warp & 3;
    const int wn   = warp >> 2;
    const int g    = lane >> 2;
    const int tg   = lane & 3;

    const int l7 = lane & 7;
    const int arow  = l7 + ((lane >> 3) & 1) * 8;
    const int ahoff = ((lane >> 4) & 1) * 8;
    const int brow  = l7 + ((lane >> 4) & 1) * 8;
    const int bhoff = ((lane >> 3) & 1) * 8;
    const uint32_t aA0 = s2u(&As[0][0][0]) + ((wm*32 + arow)*40 + ahoff)*2;
    const uint32_t aB0 = s2u(&Bs[0][0][0]) + ((wn*64 + brow)*40 + bhoff)*2;

    // cp.async chunk mapping: 512 chunks (128 rows x 4) per operand, 2/thread
    const int r0c = t >> 2, kc = (t & 3);
    const int r1c = r0c + 64;
    const uint32_t smA0 = s2u(&As[0][0][0]) + r0c*80 + kc*16;
    const uint32_t smA1 = s2u(&As[0][0][0]) + r1c*80 + kc*16;
    const uint32_t smB0 = s2u(&Bs[0][0][0]) + r0c*80 + kc*16;
    const uint32_t smB1 = s2u(&Bs[0][0][0]) + r1c*80 + kc*16;
    const __half* gA0 = A + (size_t)(m0 + r0c)*lda + kc*8;
    const __half* gA1 = A + (size_t)(m0 + r1c)*lda + kc*8;
    const __half* gB0 = B + (size_t)(n0 + r0c)*ldb + kc*8;
    const __half* gB1 = B + (size_t)(n0 + r1c)*ldb + kc*8;
    const bool okA0 = (m0 + r0c) < M, okA1 = (m0 + r1c) < M;
    const bool okB0 = (n0 + r0c) < N, okB1 = (n0 + r1c) < N;

    float acc[2][8][4];
    #pragma unroll
    for (int i = 0; i < 2; i++)
        #pragma unroll
        for (int j = 0; j < 8; j++)
            #pragma unroll
            for (int q = 0; q < 4; q++) acc[i][j][q] = 0.f;

    CPA(smA0, gA0, okA0); CPA(smA1, gA1, okA1);
    CPA(smB0, gB0, okB0); CPA(smB1, gB1, okB1);
    CPCOMMIT;

    int s = 0;
    for (int k0 = 0; k0 < K; k0 += 32, s ^= 1) {
        CPWAIT0;
        __syncthreads();
        if (k0 + 32 < K) {
            const uint32_t so = (s ^ 1) * 10240;
            CPA(smA0 + so, gA0 + k0 + 32, okA0); CPA(smA1 + so, gA1 + k0 + 32, okA1);
            CPA(smB0 + so, gB0 + k0 + 32, okB0); CPA(smB1 + so, gB1 + k0 + 32, okB1);
        }
        CPCOMMIT;

        const uint32_t so = s * 10240;
        #pragma unroll
        for (int ks = 0; ks < 2; ks++) {
            const uint32_t ko = so + ks*32;
            unsigned af[2][4], bf[8][2];
            LDSM4(af[0][0], af[0][1], af[0][2], af[0][3], aA0 + ko);
            LDSM4(af[1][0], af[1][1], af[1][2], af[1][3], aA0 + 1280 + ko);
            #pragma unroll
            for (int p = 0; p < 4; p++)
                LDSM4(bf[2*p][0], bf[2*p][1], bf[2*p+1][0], bf[2*p+1][1],
                      aB0 + p*1280 + ko);
            #pragma unroll
            for (int mt = 0; mt < 2; mt++)
                #pragma unroll
                for (int nt = 0; nt < 8; nt++)
                    mma16(acc[mt][nt], af[mt], bf[nt]);
        }
    }

    #pragma unroll
    for (int mt = 0; mt < 2; mt++) {
        int r0 = m0 + wm*32 + mt*16 + g;
        int r1 = r0 + 8;
        int b0 = r0 / rows_per_b;
        int b1 = r1 / rows_per_b;
        float p0 = 0.f, p1 = 0.f;
        #pragma unroll
        for (int nt = 0; nt < 8; nt++) {
            int c0 = n0 + wn*64 + nt*8 + tg*2;
            int c1 = c0 + 1;
            if (ACT == 2) {
                p0 += tanhf(acc[mt][nt][0] + aux[(size_t)b0*N + c0]) * vvec[c0];
                p0 += tanhf(acc[mt][nt][1] + aux[(size_t)b0*N + c1]) * vvec[c1];
                p1 += tanhf(acc[mt][nt][2] + aux[(size_t)b1*N + c0]) * vvec[c0];
                p1 += tanhf(acc[mt][nt][3] + aux[(size_t)b1*N + c1]) * vvec[c1];
            } else {
                p0 += tanhf(acc[mt][nt][0] + bias[c0]) * aux[(size_t)b0*N + c0];
                p0 += tanhf(acc[mt][nt][1] + bias[c1]) * aux[(size_t)b0*N + c1];
                p1 += tanhf(acc[mt][nt][2] + bias[c0]) * aux[(size_t)b1*N + c0];
                p1 += tanhf(acc[mt][nt][3] + bias[c1]) * aux[(size_t)b1*N + c1];
            }
        }
        p0 += __shfl_xor_sync(0xffffffff, p0, 1);
        p0 += __shfl_xor_sync(0xffffffff, p0, 2);
        p1 += __shfl_xor_sync(0xffffffff, p1, 1);
        p1 += __shfl_xor_sync(0xffffffff, p1, 2);
        if (tg == 0) {
            if (ACT == 2) {
                if (r0 < M) atomicAdd(&C[b0*sStride + sOff + (r0 - b0*rows_per_b)], p0);
                if (r1 < M) atomicAdd(&C[b1*sStride + sOff + (r1 - b1*rows_per_b)], p1);
            } else {
                if (r0 < M) atomicAdd(&C[r0], p0);
                if (r1 < M) atomicAdd(&C[r1], p1);
            }
        }
    }
}

// attention: 3 segments in one launch
__global__ void __launch_bounds__(256, 2)
gemm_attn3(const __half* __restrict__ uh, const __half* __restrict__ mh,
           const __half* __restrict__ pzh, const __half* __restrict__ wa,
           const float* __restrict__ hidp, const float* __restrict__ vvec,
           float* __restrict__ s_out)
{
    const int z = blockIdx.z;
    const __half* A; int M, rpb, sOff;
    if (z == 0)      { A = uh;  M = BB*TU; rpb = TU; sOff = 0; }
    else if (z == 1) { A = mh;  M = BB*TM; rpb = TM; sOff = TU; }
    else             { if (blockIdx.y >= 8) return;
                       A = pzh; M = BB*TZ; rpb = TZ; sOff = TU+TM; }
    gemmh_body<2>(A, HH, wa + HH, 2*HH, nullptr, hidp, vvec, s_out,
                  M, HH, HH, rpb, blockIdx.y*128, blockIdx.x*128, sOff, TT);
}

// copy scores: 3 segments in one launch
__global__ void __launch_bounds__(256, 2)
gemm_cp3(const __half* __restrict__ uh, const __half* __restrict__ mh,
         const __half* __restrict__ pzh,
         const __half* __restrict__ wu, const __half* __restrict__ wm,
         const __half* __restrict__ wz,
         const float* __restrict__ bu, const float* __restrict__ bm,
         const float* __restrict__ bz,
         const float* __restrict__ st, float* __restrict__ sc)
{
    const int z = blockIdx.z;
    const __half *A, *B; const float* bias; float* C; int M, rpb;
    if (z == 0)      { A = uh;  B = wu; bias = bu; C = sc;              M = BB*TU; rpb = TU; }
    else if (z == 1) { A = mh;  B = wm; bias = bm; C = sc + BB*TU;      M = BB*TM; rpb = TM; }
    else             { if (blockIdx.y >= 8) return;
                       A = pzh; B = wz; bias = bz; C = sc + BB*(TU+TM); M = BB*TZ; rpb = TZ; }
    gemmh_body<3>(A, HH, B, HH, bias, st, nullptr, C,
                  M, SS, HH, rpb, blockIdx.y*128, blockIdx.x*128, 0, 0);
}

// ============== 32x256 GEMM for M=32 (A fp32, B fp16 via cp.async) ==========
__device__ __forceinline__ void
gemm32_body(const float* __restrict__ A, int lda,
            const __half* __restrict__ B, int ldb,
            const float* __restrict__ bias,
            float* __restrict__ C, int ldc,
            int N, int K, int n0)
{
    __shared__ __half2 As[2][32][20];    // stage stride 2560 B
    __shared__ __half2 Bs[2][256][20];   // stage stride 20480 B

    const int t    = threadIdx.x;
    const int warp = t >> 5;
    const int lane = t & 31;
    const int wn   = warp;
    const int g    = lane >> 2;
    const int tg   = lane & 3;

    const int l7 = lane & 7;
    const int arow  = l7 + ((lane >> 3) & 1) * 8;
    const int ahoff = ((lane >> 4) & 1) * 8;
    const int brow  = l7 + ((lane >> 4) & 1) * 8;
    const int bhoff = ((lane >> 3) & 1) * 8;
    const uint32_t aA0 = s2u(&As[0][0][0]) + (arow*40 + ahoff)*2;
    const uint32_t aB0 = s2u(&Bs[0][0][0]) + ((wn*32 + brow)*40 + bhoff)*2;

    const int alr = t >> 3, alc = (t & 7) * 4;
    const float* Ap = A + (size_t)alr * lda + alc;

    uint32_t smB[4]; const __half* gB[4]; bool okB[4];
    #pragma unroll
    for (int i = 0; i < 4; i++) {
        int c = t + i*256, row = c >> 2, kcc = c & 3;
        smB[i] = s2u(&Bs[0][0][0]) + row*80 + kcc*16;
        gB[i]  = B + (size_t)(n0 + row)*ldb + kcc*8;
        okB[i] = (n0 + row) < N;
    }

    float acc[2][4][4];
    #pragma unroll
    for (int i = 0; i < 2; i++)
        #pragma unroll
        for (int j = 0; j < 4; j++)
            #pragma unroll
            for (int q = 0; q < 4; q++) acc[i][j][q] = 0.f;

    float4 av = *(const float4*)(Ap);
    #pragma unroll
    for (int i = 0; i < 4; i++) CPA(smB[i], gB[i], okB[i]);
    CPCOMMIT;

    int s = 0;
    for (int k0 = 0; k0 < K; k0 += 32, s ^= 1) {
        CPWAIT0;
        As[s][alr][alc/2    ] = __floats2half2_rn(av.x, av.y);
        As[s][alr][alc/2 + 1] = __floats2half2_rn(av.z, av.w);
        __syncthreads();
        if (k0 + 32 < K) {
            av = *(const float4*)(Ap + k0 + 32);
            const uint32_t so = (s ^ 1) * 20480;
            #pragma unroll
            for (int i = 0; i < 4; i++) CPA(smB[i] + so, gB[i] + k0 + 32, okB[i]);
        }
        CPCOMMIT;

        const uint32_t soA = s * 2560, soB = s * 20480;
        #pragma unroll
        for (int ks = 0; ks < 2; ks++) {
            unsigned af[2][4], bf[4][2];
            LDSM4(af[0][0], af[0][1], af[0][2], af[0][3], aA0 + soA + ks*32);
            LDSM4(af[1][0], af[1][1], af[1][2], af[1][3], aA0 + 1280 + soA + ks*32);
            #pragma unroll
            for (int p = 0; p < 2; p++)
                LDSM4(bf[2*p][0], bf[2*p][1], bf[2*p+1][0], bf[2*p+1][1],
                      aB0 + p*1280 + soB + ks*32);
            #pragma unroll
            for (int mt = 0; mt < 2; mt++)
                #pragma unroll
                for (int nt = 0; nt < 4; nt++)
                    mma16(acc[mt][nt], af[mt], bf[nt]);
        }
    }

    #pragma unroll
    for (int mt = 0; mt < 2; mt++) {
        int r0 = mt*16 + g;
        int r1 = r0 + 8;
        #pragma unroll
        for (int nt = 0; nt < 4; nt++) {
            int c0 = n0 + wn*32 + nt*8 + tg*2;
            float bb0 = bias ? bias[min(c0,   N-1)] : 0.f;
            float bb1 = bias ? bias[min(c0+1, N-1)] : 0.f;
            if (c0   < N) {
                C[(size_t)r0*ldc + c0] = acc[mt][nt][0] + bb0;
                C[(size_t)r1*ldc + c0] = acc[mt][nt][2] + bb0;
            }
            if (c0+1 < N) {
                C[(size_t)r0*ldc + c0+1] = acc[mt][nt][1] + bb1;
                C[(size_t)r1*ldc + c0+1] = acc[mt][nt][3] + bb1;
            }
        }
    }
}

__global__ void __launch_bounds__(256, 1)
gemm_h32(const float* __restrict__ A, int lda, const __half* __restrict__ B, int ldb,
         const float* __restrict__ bias, float* __restrict__ C, int ldc, int N, int K)
{
    gemm32_body(A, lda, B, ldb, bias, C, ldc, N, K, blockIdx.x * 256);
}

__global__ void __launch_bounds__(256, 1)
gemm_h32_pair(const float* __restrict__ A0, int lda0, const __half* __restrict__ B0,
              int ldb0, const float* __restrict__ bias0, float* __restrict__ C0, int K0,
              const float* __restrict__ A1, int lda1, const __half* __restrict__ B1,
              int ldb1, const float* __restrict__ bias1, float* __restrict__ C1, int K1)
{
    if (blockIdx.y == 0)
        gemm32_body(A0, lda0, B0, ldb0, bias0, C0, 3*HH, 3*HH, K0, blockIdx.x * 256);
    else
        gemm32_body(A1, lda1, B1, ldb1, bias1, C1, 3*HH, 3*HH, K1, blockIdx.x * 256);
}

// ---------------- small kernels -------------------------------------------
// softmax (recomputed per block) + 32-wide t-chunked context (chunks never cross segments)
__global__ void attn_ctx2(const float* __restrict__ s, const float* __restrict__ u,
                          const float* __restrict__ m, const float* __restrict__ pz,
                          const float* __restrict__ emb, float* __restrict__ x)
{
    int b = blockIdx.y, tid = threadIdx.x, z = blockIdx.z;   // 128 threads
    __shared__ float red[128];
    __shared__ float sw[TT];
    float mx = -1e30f;
    for (int t = tid; t < TT; t += 128) { float v = s[b*TT + t]; sw[t] = v; mx = fmaxf(mx, v); }
    red[tid] = mx; __syncthreads();
    for (int o = 64; o > 0; o >>= 1) { if (tid < o) red[tid] = fmaxf(red[tid], red[tid+o]); __syncthreads(); }
    mx = red[0];
    __syncthreads();
    float sm = 0.f;
    for (int t = tid; t < TT; t += 128) { float e = expf(sw[t] - mx); sw[t] = e; sm += e; }
    red[tid] = sm; __syncthreads();
    for (int o = 64; o > 0; o >>= 1) { if (tid < o) red[tid] += red[tid+o]; __syncthreads(); }
    float inv = 1.f / red[0];
    __syncthreads();

    int h = blockIdx.x * 128 + tid;
    const float* src; int trow;
    if (z < 4)      { src = u;  trow = b*TU + z*32; }
    else if (z < 8) { src = m;  trow = b*TM + (z-4)*32; }
    else            { src = pz; trow = b*TZ; }
    const float* eb = src + (size_t)trow*HH + h;
    float acc = 0.f;
    #pragma unroll
    for (int t = 0; t < 32; t++)
        acc += sw[z*32 + t] * eb[(size_t)t*HH];
    atomicAdd(&x[b*SS + EE + h], acc * inv);
    if (blockIdx.x == 0 && z == 0) x[b*SS + tid] = emb[b*EE + tid];   // EE == 128
}

__global__ void gru_gate(const float* __restrict__ gi, const float* __restrict__ gh,
                         const float* __restrict__ h0, const float* __restrict__ emb,
                         float* __restrict__ hnew, float* __restrict__ st,
                         float* __restrict__ out_lh, float* __restrict__ out_go)
{
    int idx = blockIdx.x*blockDim.x + threadIdx.x;
    if (idx >= BB*HH) return;
    int b = idx / HH, i = idx % HH;
    const float* gib = gi + (size_t)b*3*HH;
    const float* ghb = gh + (size_t)b*3*HH;
    float r = 1.f / (1.f + expf(-(gib[i]        + ghb[i]       )));
    float z = 1.f / (1.f + expf(-(gib[HH + i]   + ghb[HH + i]  )));
    float n = tanhf(gib[2*HH + i] + r * ghb[2*HH + i]);
    float h = (1.f - z) * n + z * h0[idx];
    hnew[idx] = h;
    st[b*SS + i] = h;
    out_lh[idx] = h;
    out_go[idx] = h;
    if (i < EE) st[b*SS + HH + i] = emb[b*EE + i];
}

// ---------------- final softmax: reduce / mix / scatter --------------------
__global__ void fo_reduce(const float* __restrict__ sg, const float* __restrict__ sc,
                          float2* __restrict__ red_out)
{
    int b = blockIdx.x, tid = threadIdx.x;
    __shared__ float red[256];
    const float* sgb  = sg + (size_t)b*VV;
    const float* scu  = sc + b*TU;
    const float* scm  = sc + BB*TU + b*TM;
    const float* scpz = sc + BB*(TU+TM) + b*TZ;

    float mx = -1e30f;
    for (int v = tid; v < VV; v += 256) mx = fmaxf(mx, sgb[v]);
    for (int t = tid; t < TU; t += 256) { mx = fmaxf(mx, scu[t]); mx = fmaxf(mx, scm[t]); }
    if (tid < TZ) mx = fmaxf(mx, scpz[tid]);
    red[tid] = mx; __syncthreads();
    for (int o = 128; o > 0; o >>= 1) { if (tid < o) red[tid] = fmaxf(red[tid], red[tid+o]); __syncthreads(); }
    mx = red[0];
    __syncthreads();

    float sm = 0.f;
    for (int v = tid; v < VV; v += 256) sm += expf(sgb[v] - mx);
    for (int t = tid; t < TU; t += 256) sm += expf(scu[t] - mx) + expf(scm[t] - mx);
    if (tid < TZ) sm += expf(scpz[tid] - mx);
    red[tid] = sm; __syncthreads();
    for (int o = 128; o > 0; o >>= 1) { if (tid < o) red[tid] += red[tid+o]; __syncthreads(); }
    if (tid == 0) red_out[b] = make_float2(mx, red[0]);
}

__global__ void fo_mix(const float* __restrict__ sg, const float* __restrict__ sc,
                       const float* __restrict__ pzprob, const float2* __restrict__ red,
                       float* __restrict__ out)
{
    int b = blockIdx.y, tid = threadIdx.x;
    __shared__ float pzp[TZ];
    float mx = red[b].x;
    float inv = 1.f / red[b].y;
    if (tid < TZ) pzp[tid] = expf(sc[BB*(TU+TM) + b*TZ + tid] - mx) * inv;
    __syncthreads();
    const float* sgb = sg + (size_t)b*VV;
    float* ob = out + (size_t)b*VV;
    int v0 = blockIdx.x * 1250;
    int v1 = min(VV, v0 + 1250);
    for (int v = v0 + tid; v < v1; v += 256) {
        float acc = expf(sgb[v] - mx) * inv;
        #pragma unroll
        for (int t = 0; t < TZ; t++)
            acc += pzp[t] * pzprob[((size_t)(b*TZ + t))*VV + v];
        ob[v] = acc;
    }
}

__global__ void fo_scatter(const float* __restrict__ sc, const float2* __restrict__ red,
                           const int* __restrict__ u_idx, const int* __restrict__ m_idx,
                           float* __restrict__ out)
{
    int b = blockIdx.x, tid = threadIdx.x;
    float mx = red[b].x;
    float inv = 1.f / red[b].y;
    const float* scu = sc + b*TU;
    const float* scm = sc + BB*TU + b*TM;
    float* ob = out + (size_t)b*VV;
    for (int t = tid; t < TU; t += 256) {
        atomicAdd(&ob[u_idx[b*TU + t]], expf(scu[t] - mx) * inv);
        atomicAdd(&ob[m_idx[b*TM + t]], expf(scm[t] - mx) * inv);
    }
}

// ---------------- launcher -------------------------------------------------
extern "C" void kernel_launch(void* const* d_in, const int* in_sizes, int n_in,
                              void* d_out, int out_size)
{
    const int*   u_input     = (const int*)  d_in[0];
    const float* u_hiddens   = (const float*)d_in[2];
    const int*   m_input     = (const int*)  d_in[3];
    const float* m_hiddens   = (const float*)d_in[5];
    const float* pv_z_prob   = (const float*)d_in[6];
    const float* pv_z_hidden = (const float*)d_in[7];
    const float* emb_zt      = (const float*)d_in[9];
    const float* last_hidden = (const float*)d_in[10];
    const float* W_attn      = (const float*)d_in[11];
    const float* b_attn      = (const float*)d_in[12];
    const float* v_attn      = (const float*)d_in[13];
    const float* W_ih        = (const float*)d_in[14];
    const float* W_hh        = (const float*)d_in[15];
    const float* b_ih        = (const float*)d_in[16];
    const float* b_hh        = (const float*)d_in[17];
    const float* W_gen       = (const float*)d_in[18];
    const float* b_gen       = (const float*)d_in[19];
    const float* W_cpu       = (const float*)d_in[20];
    const float* b_cpu       = (const float*)d_in[21];
    const float* W_cpm       = (const float*)d_in[22];
    const float* b_cpm       = (const float*)d_in[23];
    const float* W_cppz      = (const float*)d_in[24];
    const float* b_cppz      = (const float*)d_in[25];
    float* out = (float*)d_out;

    float *hidp, *s, *x, *gi, *gh, *hn, *st, *sc, *sg;
    float2* red;
    __half *uh, *mh, *pzh, *wah, *wihh, *whhh, *wgenh, *wcuh, *wcmh, *wczh;
    cudaGetSymbolAddress((void**)&hidp, g_hidp);
    cudaGetSymbolAddress((void**)&s,    g_s);
    cudaGetSymbolAddress((void**)&x,    g_x);
    cudaGetSymbolAddress((void**)&gi,   g_gi);
    cudaGetSymbolAddress((void**)&gh,   g_gh);
    cudaGetSymbolAddress((void**)&hn,   g_h);
    cudaGetSymbolAddress((void**)&st,   g_st);
    cudaGetSymbolAddress((void**)&sc,   g_sc);
    cudaGetSymbolAddress((void**)&sg,   g_sg);
    cudaGetSymbolAddress((void**)&red,  g_red);
    cudaGetSymbolAddress((void**)&uh,   h_uh);
    cudaGetSymbolAddress((void**)&mh,   h_mh);
    cudaGetSymbolAddress((void**)&pzh,  h_pzh);
    cudaGetSymbolAddress((void**)&wah,  h_Wattn);
    cudaGetSymbolAddress((void**)&wihh, h_Wih);
    cudaGetSymbolAddress((void**)&whhh, h_Whh);
    cudaGetSymbolAddress((void**)&wgenh,h_Wgen);
    cudaGetSymbolAddress((void**)&wcuh, h_Wcpu);
    cudaGetSymbolAddress((void**)&wcmh, h_Wcpm);
    cudaGetSymbolAddress((void**)&wczh, h_Wcppz);

    // one-time side stream + events (topology identical every call)
    static cudaStream_t s1 = nullptr;
    static cudaEvent_t evF, evH, evW, evG, evS;
    if (!s1) {
        cudaStreamCreateWithFlags(&s1, cudaStreamNonBlocking);
        cudaEventCreateWithFlags(&evF, cudaEventDisableTiming);
        cudaEventCreateWithFlags(&evH, cudaEventDisableTiming);
        cudaEventCreateWithFlags(&evW, cudaEventDisableTiming);
        cudaEventCreateWithFlags(&evG, cudaEventDisableTiming);
        cudaEventCreateWithFlags(&evS, cudaEventDisableTiming);
    }

    // fork: hidp (fp32 SIMT) + weight conversions on s1; act conversions on s0
    cudaEventRecord(evF, 0);
    cudaStreamWaitEvent(s1, evF, 0);
    hidp_k<<<HH, 256, 0, s1>>>(last_hidden, W_attn, b_attn, hidp);
    cudaEventRecord(evH, s1);
    cvt_rest<<<8938, 256, 0, s1>>>((const float4*)W_ih, (const float4*)W_hh,
                                   (const float4*)W_gen, (const float4*)W_cpu,
                                   (const float4*)W_cpm, (const float4*)W_cppz);
    cudaEventRecord(evW, s1);

    cvt_act<<<5120, 256>>>((const float4*)u_hiddens, (const float4*)m_hiddens,
                           (const float4*)pv_z_hidden, (const float4*)W_attn);
    cudaMemsetAsync(s, 0, BB*TT*sizeof(float));
    cudaMemsetAsync(x, 0, BB*SS*sizeof(float));
    // attention scores (3 segments, fused tanh-dot epilogue); needs hidp
    cudaStreamWaitEvent(0, evH, 0);
    gemm_attn3<<<dim3(4, 32, 3), 256>>>(uh, mh, pzh, wah, hidp, v_attn, s);
    // softmax + context + x assembly
    attn_ctx2<<<dim3(HH/128, BB, 9), 128>>>(s, u_hiddens, m_hiddens, pv_z_hidden,
                                            emb_zt, x);
    // join weights, GRU GEMMs, gates
    cudaStreamWaitEvent(0, evW, 0);
    gemm_h32_pair<<<dim3(6, 2), 256>>>(x, SS, wihh, SS, b_ih, gi, SS,
                                       last_hidden, HH, whhh, HH, b_hh, gh, HH);
    gru_gate<<<(BB*HH + 255)/256, 256>>>(gi, gh, last_hidden, emb_zt, hn, st,
                                         out + BB*VV, out + BB*VV + BB*HH);
    // fork: sg GEMM on s1 parallel with copy-score GEMMs on s0
    cudaEventRecord(evG, 0);
    cudaStreamWaitEvent(s1, evG, 0);
    gemm_h32<<<40, 256, 0, s1>>>(st, SS, wgenh, SS, b_gen, sg, VV, VV, SS);
    cudaEventRecord(evS, s1);

    cudaMemsetAsync(sc, 0, NROW_P*sizeof(float));
    gemm_cp3<<<dim3(5, 32, 3), 256>>>(uh, mh, pzh, wcuh, wcmh, wczh,
                                      b_cpu, b_cpm, b_cppz, st, sc);
    cudaStreamWaitEvent(0, evS, 0);
    // joint softmax + pointer mixture + scatter
    fo_reduce<<<BB, 256>>>(sg, sc, red);
    fo_mix<<<dim3(8, BB), 256>>>(sg, sc, pv_z_prob, red, out);
    fo_scatter<<<BB, 256>>>(sc, red, u_input, m_input, out);
}

// round 12
// speedup vs baseline: 1.1856x; 1.1856x over previous
#include <cuda_runtime.h>
#include <cuda_fp16.h>
#include <math.h>
#include <stdint.h>

#define BB 32
#define TU 128
#define TM 128
#define TZ 32
#define TT 288          // TU+TM+TZ
#define HH 512
#define EE 128
#define SS 640          // E+H
#define VV 10000
#define NROW_P 9216     // BB*(TU+TM+TZ)

// ---------------- scratch (device globals; no allocation allowed) ----------
__device__ float g_hidp[BB*HH];
__device__ float g_s[BB*TT];
__device__ float g_x[BB*SS];
__device__ float g_gi[BB*3*HH];
__device__ float g_gh[BB*3*HH];
__device__ float g_h[BB*HH];
__device__ float g_st[BB*SS];
__device__ float g_sc[NROW_P];
__device__ float g_sg[BB*VV];
__device__ float2 g_red[BB];

// fp16 converted operands
__device__ __half h_uh[BB*TU*HH];
__device__ __half h_mh[BB*TM*HH];
__device__ __half h_pzh[BB*TZ*HH];
__device__ __half h_Wattn[HH*2*HH];
__device__ __half h_Wih[3*HH*SS];
__device__ __half h_Whh[3*HH*HH];
__device__ __half h_Wgen[VV*SS];
__device__ __half h_Wcpu[SS*HH];
__device__ __half h_Wcpm[SS*HH];
__device__ __half h_Wcppz[SS*HH];

// ---------------- helpers ---------------------------------------------------
__device__ __forceinline__ uint32_t s2u(const void* p) {
    unsigned a;
    asm("{ .reg .u64 t; cvta.to.shared.u64 t, %1; cvt.u32.u64 %0, t; }" : "=r"(a) : "l"(p));
    return a;
}

#define LDSM4(r0, r1, r2, r3, a) \
    asm volatile("ldmatrix.sync.aligned.m8n8.x4.shared.b16 {%0,%1,%2,%3}, [%4];" \
                 : "=r"(r0), "=r"(r1), "=r"(r2), "=r"(r3) : "r"(a))

__device__ __forceinline__ void mma16(float* c, const unsigned* a, const unsigned* b) {
    asm volatile(
        "mma.sync.aligned.m16n8k16.row.col.f32.f16.f16.f32 "
        "{%0,%1,%2,%3}, {%4,%5,%6,%7}, {%8,%9}, {%0,%1,%2,%3};\n"
        : "+f"(c[0]), "+f"(c[1]), "+f"(c[2]), "+f"(c[3])
        : "r"(a[0]), "r"(a[1]), "r"(a[2]), "r"(a[3]), "r"(b[0]), "r"(b[1]));
}

#define CPA(sm, gm, ok) \
    asm volatile("cp.async.ca.shared.global [%0], [%1], 16, %2;\n" \
                 :: "r"(sm), "l"(gm), "r"((ok) ? 16 : 0) : "memory")
#define CPCOMMIT asm volatile("cp.async.commit_group;\n" ::: "memory")
#define CPWAIT0  asm volatile("cp.async.wait_group 0;\n" ::: "memory")

// ---------------- fp32 -> fp16 conversion (2 batched kernels) --------------
__global__ void cvt_act(const float4* __restrict__ u, const float4* __restrict__ m,
                        const float4* __restrict__ pz, const float4* __restrict__ wa)
{
    size_t i = (size_t)blockIdx.x*256 + threadIdx.x;
    const size_t n0 = 524288, n1 = n0 + 524288, n2 = n1 + 131072, n3 = n2 + 131072;
    const float4* src; __half2* dst; size_t off;
    if (i < n0)      { src = u;  dst = (__half2*)h_uh;    off = i; }
    else if (i < n1) { src = m;  dst = (__half2*)h_mh;    off = i - n0; }
    else if (i < n2) { src = pz; dst = (__half2*)h_pzh;   off = i - n1; }
    else if (i < n3) { src = wa; dst = (__half2*)h_Wattn; off = i - n2; }
    else return;
    float4 v = src[off];
    __half2 a = __floats2half2_rn(v.x, v.y), b = __floats2half2_rn(v.z, v.w);
    uint2 o; o.x = *(unsigned*)&a; o.y = *(unsigned*)&b;
    *(uint2*)&dst[2*off] = o;
}

__global__ void cvt_rest(const float4* __restrict__ wih, const float4* __restrict__ whh,
                         const float4* __restrict__ wgen, const float4* __restrict__ wcu,
                         const float4* __restrict__ wcm, const float4* __restrict__ wcz)
{
    size_t i = (size_t)blockIdx.x*256 + threadIdx.x;
    const size_t n0 = 245760, n1 = n0+196608, n2 = n1+1600000,
                 n3 = n2+81920, n4 = n3+81920, n5 = n4+81920;
    const float4* src; __half2* dst; size_t off;
    if (i < n0)      { src = wih;  dst = (__half2*)h_Wih;   off = i; }
    else if (i < n1) { src = whh;  dst = (__half2*)h_Whh;   off = i - n0; }
    else if (i < n2) { src = wgen; dst = (__half2*)h_Wgen;  off = i - n1; }
    else if (i < n3) { src = wcu;  dst = (__half2*)h_Wcpu;  off = i - n2; }
    else if (i < n4) { src = wcm;  dst = (__half2*)h_Wcpm;  off = i - n3; }
    else if (i < n5) { src = wcz;  dst = (__half2*)h_Wcppz; off = i - n4; }
    else return;
    float4 v = src[off];
    __half2 a = __floats2half2_rn(v.x, v.y), b = __floats2half2_rn(v.z, v.w);
    uint2 o; o.x = *(unsigned*)&a; o.y = *(unsigned*)&b;
    *(uint2*)&dst[2*off] = o;
}

// ============== 128x128 fp16 GEMM body (cp.async + ldmatrix) ================
// ACT 2: atomicAdd(C[b*sStride + sOff + t], sum_n tanh(acc + aux[b*N+n])*vvec[n])
// ACT 3: atomicAdd(C[r], sum_n tanh(acc + bias[n]) * aux[b*N+n]), b = r/rows_per_b
template<int ACT>
__device__ __forceinline__ void
gemmh_body(const __half* __restrict__ A, int lda,
           const __half* __restrict__ B, int ldb,
           const float* __restrict__ bias,
           const float* __restrict__ aux,
           const float* __restrict__ vvec,
           float* __restrict__ C,
           int M, int N, int K, int rows_per_b,
           int m0, int n0, int sOff, int sStride)
{
    __shared__ __half2 As[2][128][20];   // 80B rows, stage stride 10240 B
    __shared__ __half2 Bs[2][128][20];

    const int t    = threadIdx.x;
    const int warp = t >> 5;
    const int lane = t & 31;
    const int wm   = warp & 3;
    const int wn   = warp >> 2;
    const int g    = lane >> 2;
    const int tg   = lane & 3;

    const int l7 = lane & 7;
    const int arow  = l7 + ((lane >> 3) & 1) * 8;
    const int ahoff = ((lane >> 4) & 1) * 8;
    const int brow  = l7 + ((lane >> 4) & 1) * 8;
    const int bhoff = ((lane >> 3) & 1) * 8;
    const uint32_t aA0 = s2u(&As[0][0][0]) + ((wm*32 + arow)*40 + ahoff)*2;
    const uint32_t aB0 = s2u(&Bs[0][0][0]) + ((wn*64 + brow)*40 + bhoff)*2;

    // cp.async chunk mapping: 512 chunks (128 rows x 4) per operand, 2/thread
    const int r0c = t >> 2, kc = (t & 3);
    const int r1c = r0c + 64;
    const uint32_t smA0 = s2u(&As[0][0][0]) + r0c*80 + kc*16;
    const uint32_t smA1 = s2u(&As[0][0][0]) + r1c*80 + kc*16;
    const uint32_t smB0 = s2u(&Bs[0][0][0]) + r0c*80 + kc*16;
    const uint32_t smB1 = s2u(&Bs[0][0][0]) + r1c*80 + kc*16;
    const __half* gA0 = A + (size_t)(m0 + r0c)*lda + kc*8;
    const __half* gA1 = A + (size_t)(m0 + r1c)*lda + kc*8;
    const __half* gB0 = B + (size_t)(n0 + r0c)*ldb + kc*8;
    const __half* gB1 = B + (size_t)(n0 + r1c)*ldb + kc*8;
    const bool okA0 = (m0 + r0c) < M, okA1 = (m0 + r1c) < M;
    const bool okB0 = (n0 + r0c) < N, okB1 = (n0 + r1c) < N;

    float acc[2][8][4];
    #pragma unroll
    for (int i = 0; i < 2; i++)
        #pragma unroll
        for (int j = 0; j < 8; j++)
            #pragma unroll
            for (int q = 0; q < 4; q++) acc[i][j][q] = 0.f;

    CPA(smA0, gA0, okA0); CPA(smA1, gA1, okA1);
    CPA(smB0, gB0, okB0); CPA(smB1, gB1, okB1);
    CPCOMMIT;

    int s = 0;
    for (int k0 = 0; k0 < K; k0 += 32, s ^= 1) {
        CPWAIT0;
        __syncthreads();
        if (k0 + 32 < K) {
            const uint32_t so = (s ^ 1) * 10240;
            CPA(smA0 + so, gA0 + k0 + 32, okA0); CPA(smA1 + so, gA1 + k0 + 32, okA1);
            CPA(smB0 + so, gB0 + k0 + 32, okB0); CPA(smB1 + so, gB1 + k0 + 32, okB1);
        }
        CPCOMMIT;

        const uint32_t so = s * 10240;
        #pragma unroll
        for (int ks = 0; ks < 2; ks++) {
            const uint32_t ko = so + ks*32;
            unsigned af[2][4], bf[8][2];
            LDSM4(af[0][0], af[0][1], af[0][2], af[0][3], aA0 + ko);
            LDSM4(af[1][0], af[1][1], af[1][2], af[1][3], aA0 + 1280 + ko);
            #pragma unroll
            for (int p = 0; p < 4; p++)
                LDSM4(bf[2*p][0], bf[2*p][1], bf[2*p+1][0], bf[2*p+1][1],
                      aB0 + p*1280 + ko);
            #pragma unroll
            for (int mt = 0; mt < 2; mt++)
                #pragma unroll
                for (int nt = 0; nt < 8; nt++)
                    mma16(acc[mt][nt], af[mt], bf[nt]);
        }
    }

    #pragma unroll
    for (int mt = 0; mt < 2; mt++) {
        int r0 = m0 + wm*32 + mt*16 + g;
        int r1 = r0 + 8;
        int b0 = r0 / rows_per_b;
        int b1 = r1 / rows_per_b;
        float p0 = 0.f, p1 = 0.f;
        #pragma unroll
        for (int nt = 0; nt < 8; nt++) {
            int c0 = n0 + wn*64 + nt*8 + tg*2;
            int c1 = c0 + 1;
            if (ACT == 2) {
                p0 += tanhf(acc[mt][nt][0] + aux[(size_t)b0*N + c0]) * vvec[c0];
                p0 += tanhf(acc[mt][nt][1] + aux[(size_t)b0*N + c1]) * vvec[c1];
                p1 += tanhf(acc[mt][nt][2] + aux[(size_t)b1*N + c0]) * vvec[c0];
                p1 += tanhf(acc[mt][nt][3] + aux[(size_t)b1*N + c1]) * vvec[c1];
            } else {
                p0 += tanhf(acc[mt][nt][0] + bias[c0]) * aux[(size_t)b0*N + c0];
                p0 += tanhf(acc[mt][nt][1] + bias[c1]) * aux[(size_t)b0*N + c1];
                p1 += tanhf(acc[mt][nt][2] + bias[c0]) * aux[(size_t)b1*N + c0];
                p1 += tanhf(acc[mt][nt][3] + bias[c1]) * aux[(size_t)b1*N + c1];
            }
        }
        p0 += __shfl_xor_sync(0xffffffff, p0, 1);
        p0 += __shfl_xor_sync(0xffffffff, p0, 2);
        p1 += __shfl_xor_sync(0xffffffff, p1, 1);
        p1 += __shfl_xor_sync(0xffffffff, p1, 2);
        if (tg == 0) {
            if (ACT == 2) {
                if (r0 < M) atomicAdd(&C[b0*sStride + sOff + (r0 - b0*rows_per_b)], p0);
                if (r1 < M) atomicAdd(&C[b1*sStride + sOff + (r1 - b1*rows_per_b)], p1);
            } else {
                if (r0 < M) atomicAdd(&C[r0], p0);
                if (r1 < M) atomicAdd(&C[r1], p1);
            }
        }
    }
}

// attention: 3 segments in one launch
__global__ void __launch_bounds__(256, 2)
gemm_attn3(const __half* __restrict__ uh, const __half* __restrict__ mh,
           const __half* __restrict__ pzh, const __half* __restrict__ wa,
           const float* __restrict__ hidp, const float* __restrict__ vvec,
           float* __restrict__ s_out)
{
    const int z = blockIdx.z;
    const __half* A; int M, rpb, sOff;
    if (z == 0)      { A = uh;  M = BB*TU; rpb = TU; sOff = 0; }
    else if (z == 1) { A = mh;  M = BB*TM; rpb = TM; sOff = TU; }
    else             { if (blockIdx.y >= 8) return;
                       A = pzh; M = BB*TZ; rpb = TZ; sOff = TU+TM; }
    gemmh_body<2>(A, HH, wa + HH, 2*HH, nullptr, hidp, vvec, s_out,
                  M, HH, HH, rpb, blockIdx.y*128, blockIdx.x*128, sOff, TT);
}

// copy scores: 3 segments in one launch
__global__ void __launch_bounds__(256, 2)
gemm_cp3(const __half* __restrict__ uh, const __half* __restrict__ mh,
         const __half* __restrict__ pzh,
         const __half* __restrict__ wu, const __half* __restrict__ wm,
         const __half* __restrict__ wz,
         const float* __restrict__ bu, const float* __restrict__ bm,
         const float* __restrict__ bz,
         const float* __restrict__ st, float* __restrict__ sc)
{
    const int z = blockIdx.z;
    const __half *A, *B; const float* bias; float* C; int M, rpb;
    if (z == 0)      { A = uh;  B = wu; bias = bu; C = sc;              M = BB*TU; rpb = TU; }
    else if (z == 1) { A = mh;  B = wm; bias = bm; C = sc + BB*TU;      M = BB*TM; rpb = TM; }
    else             { if (blockIdx.y >= 8) return;
                       A = pzh; B = wz; bias = bz; C = sc + BB*(TU+TM); M = BB*TZ; rpb = TZ; }
    gemmh_body<3>(A, HH, B, HH, bias, st, nullptr, C,
                  M, SS, HH, rpb, blockIdx.y*128, blockIdx.x*128, 0, 0);
}

// ============== 32x256 GEMM for M=32 (A fp32, B fp16 via cp.async) ==========
__device__ __forceinline__ void
gemm32_body(const float* __restrict__ A, int lda,
            const __half* __restrict__ B, int ldb,
            const float* __restrict__ bias,
            float* __restrict__ C, int ldc,
            int N, int K, int n0)
{
    __shared__ __half2 As[2][32][20];    // stage stride 2560 B
    __shared__ __half2 Bs[2][256][20];   // stage stride 20480 B

    const int t    = threadIdx.x;
    const int warp = t >> 5;
    const int lane = t & 31;
    const int wn   = warp;
    const int g    = lane >> 2;
    const int tg   = lane & 3;

    const int l7 = lane & 7;
    const int arow  = l7 + ((lane >> 3) & 1) * 8;
    const int ahoff = ((lane >> 4) & 1) * 8;
    const int brow  = l7 + ((lane >> 4) & 1) * 8;
    const int bhoff = ((lane >> 3) & 1) * 8;
    const uint32_t aA0 = s2u(&As[0][0][0]) + (arow*40 + ahoff)*2;
    const uint32_t aB0 = s2u(&Bs[0][0][0]) + ((wn*32 + brow)*40 + bhoff)*2;

    const int alr = t >> 3, alc = (t & 7) * 4;
    const float* Ap = A + (size_t)alr * lda + alc;

    uint32_t smB[4]; const __half* gB[4]; bool okB[4];
    #pragma unroll
    for (int i = 0; i < 4; i++) {
        int c = t + i*256, row = c >> 2, kcc = c & 3;
        smB[i] = s2u(&Bs[0][0][0]) + row*80 + kcc*16;
        gB[i]  = B + (size_t)(n0 + row)*ldb + kcc*8;
        okB[i] = (n0 + row) < N;
    }

    float acc[2][4][4];
    #pragma unroll
    for (int i = 0; i < 2; i++)
        #pragma unroll
        for (int j = 0; j < 4; j++)
            #pragma unroll
            for (int q = 0; q < 4; q++) acc[i][j][q] = 0.f;

    float4 av = *(const float4*)(Ap);
    #pragma unroll
    for (int i = 0; i < 4; i++) CPA(smB[i], gB[i], okB[i]);
    CPCOMMIT;

    int s = 0;
    for (int k0 = 0; k0 < K; k0 += 32, s ^= 1) {
        CPWAIT0;
        As[s][alr][alc/2    ] = __floats2half2_rn(av.x, av.y);
        As[s][alr][alc/2 + 1] = __floats2half2_rn(av.z, av.w);
        __syncthreads();
        if (k0 + 32 < K) {
            av = *(const float4*)(Ap + k0 + 32);
            const uint32_t so = (s ^ 1) * 20480;
            #pragma unroll
            for (int i = 0; i < 4; i++) CPA(smB[i] + so, gB[i] + k0 + 32, okB[i]);
        }
        CPCOMMIT;

        const uint32_t soA = s * 2560, soB = s * 20480;
        #pragma unroll
        for (int ks = 0; ks < 2; ks++) {
            unsigned af[2][4], bf[4][2];
            LDSM4(af[0][0], af[0][1], af[0][2], af[0][3], aA0 + soA + ks*32);
            LDSM4(af[1][0], af[1][1], af[1][2], af[1][3], aA0 + 1280 + soA + ks*32);
            #pragma unroll
            for (int p = 0; p < 2; p++)
                LDSM4(bf[2*p][0], bf[2*p][1], bf[2*p+1][0], bf[2*p+1][1],
                      aB0 + p*1280 + soB + ks*32);
            #pragma unroll
            for (int mt = 0; mt < 2; mt++)
                #pragma unroll
                for (int nt = 0; nt < 4; nt++)
                    mma16(acc[mt][nt], af[mt], bf[nt]);
        }
    }

    #pragma unroll
    for (int mt = 0; mt < 2; mt++) {
        int r0 = mt*16 + g;
        int r1 = r0 + 8;
        #pragma unroll
        for (int nt = 0; nt < 4; nt++) {
            int c0 = n0 + wn*32 + nt*8 + tg*2;
            float bb0 = bias ? bias[min(c0,   N-1)] : 0.f;
            float bb1 = bias ? bias[min(c0+1, N-1)] : 0.f;
            if (c0   < N) {
                C[(size_t)r0*ldc + c0] = acc[mt][nt][0] + bb0;
                C[(size_t)r1*ldc + c0] = acc[mt][nt][2] + bb0;
            }
            if (c0+1 < N) {
                C[(size_t)r0*ldc + c0+1] = acc[mt][nt][1] + bb1;
                C[(size_t)r1*ldc + c0+1] = acc[mt][nt][3] + bb1;
            }
        }
    }
}

__global__ void __launch_bounds__(256, 1)
gemm_h32(const float* __restrict__ A, int lda, const __half* __restrict__ B, int ldb,
         const float* __restrict__ bias, float* __restrict__ C, int ldc, int N, int K)
{
    gemm32_body(A, lda, B, ldb, bias, C, ldc, N, K, blockIdx.x * 256);
}

__global__ void __launch_bounds__(256, 1)
gemm_h32_pair(const float* __restrict__ A0, int lda0, const __half* __restrict__ B0,
              int ldb0, const float* __restrict__ bias0, float* __restrict__ C0, int K0,
              const float* __restrict__ A1, int lda1, const __half* __restrict__ B1,
              int ldb1, const float* __restrict__ bias1, float* __restrict__ C1, int K1)
{
    if (blockIdx.y == 0)
        gemm32_body(A0, lda0, B0, ldb0, bias0, C0, 3*HH, 3*HH, K0, blockIdx.x * 256);
    else
        gemm32_body(A1, lda1, B1, ldb1, bias1, C1, 3*HH, 3*HH, K1, blockIdx.x * 256);
}

// ---------------- small kernels -------------------------------------------
// softmax (recomputed per block) + 32-wide t-chunked context (chunks never cross segments)
__global__ void attn_ctx2(const float* __restrict__ s, const float* __restrict__ u,
                          const float* __restrict__ m, const float* __restrict__ pz,
                          const float* __restrict__ emb, float* __restrict__ x)
{
    int b = blockIdx.y, tid = threadIdx.x, z = blockIdx.z;   // 128 threads
    __shared__ float red[128];
    __shared__ float sw[TT];
    float mx = -1e30f;
    for (int t = tid; t < TT; t += 128) { float v = s[b*TT + t]; sw[t] = v; mx = fmaxf(mx, v); }
    red[tid] = mx; __syncthreads();
    for (int o = 64; o > 0; o >>= 1) { if (tid < o) red[tid] = fmaxf(red[tid], red[tid+o]); __syncthreads(); }
    mx = red[0];
    __syncthreads();
    float sm = 0.f;
    for (int t = tid; t < TT; t += 128) { float e = expf(sw[t] - mx); sw[t] = e; sm += e; }
    red[tid] = sm; __syncthreads();
    for (int o = 64; o > 0; o >>= 1) { if (tid < o) red[tid] += red[tid+o]; __syncthreads(); }
    float inv = 1.f / red[0];
    __syncthreads();

    int h = blockIdx.x * 128 + tid;
    const float* src; int trow;
    if (z < 4)      { src = u;  trow = b*TU + z*32; }
    else if (z < 8) { src = m;  trow = b*TM + (z-4)*32; }
    else            { src = pz; trow = b*TZ; }
    const float* eb = src + (size_t)trow*HH + h;
    float acc = 0.f;
    #pragma unroll
    for (int t = 0; t < 32; t++)
        acc += sw[z*32 + t] * eb[(size_t)t*HH];
    atomicAdd(&x[b*SS + EE + h], acc * inv);
    if (blockIdx.x == 0 && z == 0) x[b*SS + tid] = emb[b*EE + tid];   // EE == 128
}

__global__ void gru_gate(const float* __restrict__ gi, const float* __restrict__ gh,
                         const float* __restrict__ h0, const float* __restrict__ emb,
                         float* __restrict__ hnew, float* __restrict__ st,
                         float* __restrict__ out_lh, float* __restrict__ out_go)
{
    int idx = blockIdx.x*blockDim.x + threadIdx.x;
    if (idx >= BB*HH) return;
    int b = idx / HH, i = idx % HH;
    const float* gib = gi + (size_t)b*3*HH;
    const float* ghb = gh + (size_t)b*3*HH;
    float r = 1.f / (1.f + expf(-(gib[i]        + ghb[i]       )));
    float z = 1.f / (1.f + expf(-(gib[HH + i]   + ghb[HH + i]  )));
    float n = tanhf(gib[2*HH + i] + r * ghb[2*HH + i]);
    float h = (1.f - z) * n + z * h0[idx];
    hnew[idx] = h;
    st[b*SS + i] = h;
    out_lh[idx] = h;
    out_go[idx] = h;
    if (i < EE) st[b*SS + HH + i] = emb[b*EE + i];
}

// ---------------- final softmax: reduce / mix / scatter --------------------
__global__ void fo_reduce(const float* __restrict__ sg, const float* __restrict__ sc,
                          float2* __restrict__ red_out)
{
    int b = blockIdx.x, tid = threadIdx.x;
    __shared__ float red[256];
    const float* sgb  = sg + (size_t)b*VV;
    const float* scu  = sc + b*TU;
    const float* scm  = sc + BB*TU + b*TM;
    const float* scpz = sc + BB*(TU+TM) + b*TZ;

    float mx = -1e30f;
    for (int v = tid; v < VV; v += 256) mx = fmaxf(mx, sgb[v]);
    for (int t = tid; t < TU; t += 256) { mx = fmaxf(mx, scu[t]); mx = fmaxf(mx, scm[t]); }
    if (tid < TZ) mx = fmaxf(mx, scpz[tid]);
    red[tid] = mx; __syncthreads();
    for (int o = 128; o > 0; o >>= 1) { if (tid < o) red[tid] = fmaxf(red[tid], red[tid+o]); __syncthreads(); }
    mx = red[0];
    __syncthreads();

    float sm = 0.f;
    for (int v = tid; v < VV; v += 256) sm += expf(sgb[v] - mx);
    for (int t = tid; t < TU; t += 256) sm += expf(scu[t] - mx) + expf(scm[t] - mx);
    if (tid < TZ) sm += expf(scpz[tid] - mx);
    red[tid] = sm; __syncthreads();
    for (int o = 128; o > 0; o >>= 1) { if (tid < o) red[tid] += red[tid+o]; __syncthreads(); }
    if (tid == 0) red_out[b] = make_float2(mx, red[0]);
}

__global__ void fo_mix(const float* __restrict__ sg, const float* __restrict__ sc,
                       const float* __restrict__ pzprob, const float2* __restrict__ red,
                       float* __restrict__ out)
{
    int b = blockIdx.y, tid = threadIdx.x;
    __shared__ float pzp[TZ];
    float mx = red[b].x;
    float inv = 1.f / red[b].y;
    if (tid < TZ) pzp[tid] = expf(sc[BB*(TU+TM) + b*TZ + tid] - mx) * inv;
    __syncthreads();
    const float* sgb = sg + (size_t)b*VV;
    float* ob = out + (size_t)b*VV;
    int v0 = blockIdx.x * 1250;
    int v1 = min(VV, v0 + 1250);
    for (int v = v0 + tid; v < v1; v += 256) {
        float acc = expf(sgb[v] - mx) * inv;
        #pragma unroll
        for (int t = 0; t < TZ; t++)
            acc += pzp[t] * pzprob[((size_t)(b*TZ + t))*VV + v];
        ob[v] = acc;
    }
}

__global__ void fo_scatter(const float* __restrict__ sc, const float2* __restrict__ red,
                           const int* __restrict__ u_idx, const int* __restrict__ m_idx,
                           float* __restrict__ out)
{
    int b = blockIdx.x, tid = threadIdx.x;
    float mx = red[b].x;
    float inv = 1.f / red[b].y;
    const float* scu = sc + b*TU;
    const float* scm = sc + BB*TU + b*TM;
    float* ob = out + (size_t)b*VV;
    for (int t = tid; t < TU; t += 256) {
        atomicAdd(&ob[u_idx[b*TU + t]], expf(scu[t] - mx) * inv);
        atomicAdd(&ob[m_idx[b*TM + t]], expf(scm[t] - mx) * inv);
    }
}

// ---------------- launcher -------------------------------------------------
extern "C" void kernel_launch(void* const* d_in, const int* in_sizes, int n_in,
                              void* d_out, int out_size)
{
    const int*   u_input     = (const int*)  d_in[0];
    const float* u_hiddens   = (const float*)d_in[2];
    const int*   m_input     = (const int*)  d_in[3];
    const float* m_hiddens   = (const float*)d_in[5];
    const float* pv_z_prob   = (const float*)d_in[6];
    const float* pv_z_hidden = (const float*)d_in[7];
    const float* emb_zt      = (const float*)d_in[9];
    const float* last_hidden = (const float*)d_in[10];
    const float* W_attn      = (const float*)d_in[11];
    const float* b_attn      = (const float*)d_in[12];
    const float* v_attn      = (const float*)d_in[13];
    const float* W_ih        = (const float*)d_in[14];
    const float* W_hh        = (const float*)d_in[15];
    const float* b_ih        = (const float*)d_in[16];
    const float* b_hh        = (const float*)d_in[17];
    const float* W_gen       = (const float*)d_in[18];
    const float* b_gen       = (const float*)d_in[19];
    const float* W_cpu       = (const float*)d_in[20];
    const float* b_cpu       = (const float*)d_in[21];
    const float* W_cpm       = (const float*)d_in[22];
    const float* b_cpm       = (const float*)d_in[23];
    const float* W_cppz      = (const float*)d_in[24];
    const float* b_cppz      = (const float*)d_in[25];
    float* out = (float*)d_out;

    float *hidp, *s, *x, *gi, *gh, *hn, *st, *sc, *sg;
    float2* red;
    __half *uh, *mh, *pzh, *wah, *wihh, *whhh, *wgenh, *wcuh, *wcmh, *wczh;
    cudaGetSymbolAddress((void**)&hidp, g_hidp);
    cudaGetSymbolAddress((void**)&s,    g_s);
    cudaGetSymbolAddress((void**)&x,    g_x);
    cudaGetSymbolAddress((void**)&gi,   g_gi);
    cudaGetSymbolAddress((void**)&gh,   g_gh);
    cudaGetSymbolAddress((void**)&hn,   g_h);
    cudaGetSymbolAddress((void**)&st,   g_st);
    cudaGetSymbolAddress((void**)&sc,   g_sc);
    cudaGetSymbolAddress((void**)&sg,   g_sg);
    cudaGetSymbolAddress((void**)&red,  g_red);
    cudaGetSymbolAddress((void**)&uh,   h_uh);
    cudaGetSymbolAddress((void**)&mh,   h_mh);
    cudaGetSymbolAddress((void**)&pzh,  h_pzh);
    cudaGetSymbolAddress((void**)&wah,  h_Wattn);
    cudaGetSymbolAddress((void**)&wihh, h_Wih);
    cudaGetSymbolAddress((void**)&whhh, h_Whh);
    cudaGetSymbolAddress((void**)&wgenh,h_Wgen);
    cudaGetSymbolAddress((void**)&wcuh, h_Wcpu);
    cudaGetSymbolAddress((void**)&wcmh, h_Wcpm);
    cudaGetSymbolAddress((void**)&wczh, h_Wcppz);

    // one-time side stream + events (topology identical every call)
    static cudaStream_t s1 = nullptr;
    static cudaEvent_t evF, evW, evG, evS;
    if (!s1) {
        cudaStreamCreateWithFlags(&s1, cudaStreamNonBlocking);
        cudaEventCreateWithFlags(&evF, cudaEventDisableTiming);
        cudaEventCreateWithFlags(&evW, cudaEventDisableTiming);
        cudaEventCreateWithFlags(&evG, cudaEventDisableTiming);
        cudaEventCreateWithFlags(&evS, cudaEventDisableTiming);
    }

    // fork: weight conversions on s1 (after act conversions), attention on s0
    cvt_act<<<5120, 256>>>((const float4*)u_hiddens, (const float4*)m_hiddens,
                           (const float4*)pv_z_hidden, (const float4*)W_attn);
    cudaEventRecord(evF, 0);
    cudaStreamWaitEvent(s1, evF, 0);
    cvt_rest<<<8938, 256, 0, s1>>>((const float4*)W_ih, (const float4*)W_hh,
                                   (const float4*)W_gen, (const float4*)W_cpu,
                                   (const float4*)W_cpm, (const float4*)W_cppz);
    cudaEventRecord(evW, s1);

    cudaMemsetAsync(s, 0, BB*TT*sizeof(float));
    cudaMemsetAsync(x, 0, BB*SS*sizeof(float));
    // hidp = h0 @ W1^T + b_attn  (W1 = cols 0..H of W_attn, fp16)
    gemm_h32<<<2, 256>>>(last_hidden, HH, wah, 2*HH, b_attn, hidp, HH, HH, HH);
    // attention scores (3 segments, fused tanh-dot epilogue)
    gemm_attn3<<<dim3(4, 32, 3), 256>>>(uh, mh, pzh, wah, hidp, v_attn, s);
    // softmax + context + x assembly
    attn_ctx2<<<dim3(HH/128, BB, 9), 128>>>(s, u_hiddens, m_hiddens, pv_z_hidden,
                                            emb_zt, x);
    // join weights, GRU GEMMs, gates
    cudaStreamWaitEvent(0, evW, 0);
    gemm_h32_pair<<<dim3(6, 2), 256>>>(x, SS, wihh, SS, b_ih, gi, SS,
                                       last_hidden, HH, whhh, HH, b_hh, gh, HH);
    gru_gate<<<(BB*HH + 255)/256, 256>>>(gi, gh, last_hidden, emb_zt, hn, st,
                                         out + BB*VV, out + BB*VV + BB*HH);
    // fork: sg GEMM on s1 parallel with copy-score GEMMs on s0
    cudaEventRecord(evG, 0);
    cudaStreamWaitEvent(s1, evG, 0);
    gemm_h32<<<40, 256, 0, s1>>>(st, SS, wgenh, SS, b_gen, sg, VV, VV, SS);
    cudaEventRecord(evS, s1);

    cudaMemsetAsync(sc, 0, NROW_P*sizeof(float));
    gemm_cp3<<<dim3(5, 32, 3), 256>>>(uh, mh, pzh, wcuh, wcmh, wczh,
                                      b_cpu, b_cpm, b_cppz, st, sc);
    cudaStreamWaitEvent(0, evS, 0);
    // joint softmax + pointer mixture + scatter
    fo_reduce<<<BB, 256>>>(sg, sc, red);
    fo_mix<<<dim3(8, BB), 256>>>(sg, sc, pv_z_prob, red, out);
    fo_scatter<<<BB, 256>>>(sc, red, u_input, m_input, out);
}